// round 6
// baseline (speedup 1.0000x reference)
#include <cuda_runtime.h>
#include <cuda.h>
#include <cstdint>

// Problem constants
#define M_TOK   64
#define K_DIM   4096
#define N_DIM   11008
#define NGRP    32           // K groups of 128
#define GRP_K   128
#define N_TILE  128
#define NUM_NT  (N_DIM / N_TILE)          // 86
#define U_TOTAL (NUM_NT * NGRP)           // 2752 group-units
#define NUM_CTAS 148
#define THREADS 512

// SMEM layout (byte offsets; tile bases 1024-aligned)
#define SM_MBAR   0            // full0, full1, empty0, empty1 (4 x 8B)
#define SM_W0     1024         // 128*128*4 = 65536
#define SM_X0     (SM_W0 + 65536)    // 66560 ; 64*128*4 = 32768
#define SM_W1     (SM_X0 + 32768)    // 99328
#define SM_X1     (SM_W1 + 65536)    // 164864
#define SM_TOTAL  (SM_X1 + 32768)    // 197632

#define STAGE_BYTES (65536 + 32768)

// scratch: x pre-rounded to nearest-tf32 (stored as f32 bit patterns)
__device__ __align__(1024) float g_x_r[M_TOK * K_DIM];

// ---------------- PTX helpers ----------------
static __device__ __forceinline__ uint32_t smem_u32(const void* p) {
    uint32_t a;
    asm("{ .reg .u64 t; cvta.to.shared.u64 t, %1; cvt.u32.u64 %0, t; }" : "=r"(a) : "l"(p));
    return a;
}

#define MBAR_INIT(addr, cnt) \
    asm volatile("mbarrier.init.shared.b64 [%0], %1;" :: "r"(addr), "r"((uint32_t)(cnt)) : "memory")

#define MBAR_EXPECT_TX(addr, bytes) \
    asm volatile("mbarrier.arrive.expect_tx.shared.b64 _, [%0], %1;" :: "r"(addr), "r"((uint32_t)(bytes)) : "memory")

#define MBAR_ARRIVE(addr) \
    asm volatile("mbarrier.arrive.shared.b64 _, [%0];" :: "r"(addr) : "memory")

#define MBAR_WAIT(addr, parity) do {                                              \
    uint32_t _mb = (addr); uint32_t _ph = (parity); uint32_t _done;               \
    asm volatile("{\n\t.reg .pred p;\n\t"                                         \
        "mbarrier.try_wait.parity.shared::cta.b64 p, [%1], %2;\n\t"               \
        "selp.b32 %0, 1, 0, p;\n\t}"                                              \
        : "=r"(_done) : "r"(_mb), "r"(_ph) : "memory");                           \
    if (!_done) {                                                                 \
        asm volatile("{\n\t.reg .pred P1;\n\t"                                    \
        "WL_%=:\n\t"                                                              \
        "mbarrier.try_wait.parity.shared::cta.b64 P1, [%0], %1, 0x989680;\n\t"    \
        "@P1 bra.uni WD_%=;\n\t"                                                  \
        "bra.uni WL_%=;\n\t"                                                      \
        "WD_%=:\n\t}" :: "r"(_mb), "r"(_ph) : "memory");                          \
    }                                                                             \
} while (0)

#define TMA_LOAD_2D(sdst, map, cx, cy, mbar) \
    asm volatile("cp.async.bulk.tensor.2d.shared::cta.global.tile.mbarrier::complete_tx::bytes " \
                 "[%0], [%1, {%2, %3}], [%4];" \
                 :: "r"(sdst), "l"(map), "r"(cx), "r"(cy), "r"(mbar) : "memory")

#define LDSM_X4(R, addr) \
    asm volatile("ldmatrix.sync.aligned.m8n8.x4.shared.b16 {%0,%1,%2,%3}, [%4];" \
        : "=r"((R)[0]), "=r"((R)[1]), "=r"((R)[2]), "=r"((R)[3]) : "r"(addr))

// m16n8k8 tf32 MMA, D += A*B (A pre-scaled floats, B uint fragments)
static __device__ __forceinline__ void mma_tf32f(
    float* d, const float* a, uint32_t b0, uint32_t b1)
{
    asm volatile(
        "mma.sync.aligned.m16n8k8.row.col.f32.tf32.tf32.f32 "
        "{%0,%1,%2,%3}, {%4,%5,%6,%7}, {%8,%9}, {%0,%1,%2,%3};"
        : "+f"(d[0]), "+f"(d[1]), "+f"(d[2]), "+f"(d[3])
        : "r"(__float_as_uint(a[0])), "r"(__float_as_uint(a[1])),
          "r"(__float_as_uint(a[2])), "r"(__float_as_uint(a[3])),
          "r"(b0), "r"(b1));
}

// ---------------- fused prologue kernel ----------------
#define X4_CNT  (M_TOK * K_DIM / 4)      // 65536
#define O4_CNT  (M_TOK * N_DIM / 4)      // 176128

__global__ void prep_kernel(const float4* __restrict__ x4, float4* __restrict__ out4)
{
    int i = blockIdx.x * blockDim.x + threadIdx.x;
    if (i < X4_CNT) {
        float4 v = x4[i];
        uint32_t r0, r1, r2, r3;
        asm("cvt.rna.tf32.f32 %0, %1;" : "=r"(r0) : "f"(v.x));
        asm("cvt.rna.tf32.f32 %0, %1;" : "=r"(r1) : "f"(v.y));
        asm("cvt.rna.tf32.f32 %0, %1;" : "=r"(r2) : "f"(v.z));
        asm("cvt.rna.tf32.f32 %0, %1;" : "=r"(r3) : "f"(v.w));
        float4 o;
        o.x = __uint_as_float(r0); o.y = __uint_as_float(r1);
        o.z = __uint_as_float(r2); o.w = __uint_as_float(r3);
        ((float4*)g_x_r)[i] = o;
    } else {
        int j = i - X4_CNT;
        if (j < O4_CNT) out4[j] = make_float4(0.f, 0.f, 0.f, 0.f);
    }
}

// ---------------- main kernel (persistent, balanced, LDSM, k-split halves) ----------------
__global__ void __launch_bounds__(THREADS, 1) qlin_kernel(
    const float* __restrict__ wscale,
    const float* __restrict__ bias,
    float* __restrict__ out,
    const __grid_constant__ CUtensorMap w_map,
    const __grid_constant__ CUtensorMap x_map)
{
    extern __shared__ char smem[];
    const uint32_t sb = smem_u32(smem);
    const int tid  = threadIdx.x;
    const int wid  = tid >> 5;
    const int lane = tid & 31;

    // Balanced contiguous range of group-units over flattened (nt, g)
    const int c  = blockIdx.x;
    const int u0 = (int)(((long long)c       * U_TOTAL) / NUM_CTAS);
    const int u1 = (int)(((long long)(c + 1) * U_TOTAL) / NUM_CTAS);
    const int nu = u1 - u0;                 // 18 or 19

    const uint32_t full0  = sb + SM_MBAR + 0;
    const uint32_t full1  = sb + SM_MBAR + 8;
    const uint32_t empty0 = sb + SM_MBAR + 16;
    const uint32_t empty1 = sb + SM_MBAR + 24;

    if (tid == 0) {
        MBAR_INIT(full0,  1);
        MBAR_INIT(full1,  1);
        MBAR_INIT(empty0, THREADS);
        MBAR_INIT(empty1, THREADS);
    }
    __syncthreads();

    // Prologue: issue stages 0 and 1 (nu >= 18 always)
    if (tid == 0) {
        #pragma unroll
        for (int pg = 0; pg < 2; pg++) {
            const int u  = u0 + pg;
            const int nt = u >> 5, g = u & 31;
            const uint32_t fb = pg ? full1 : full0;
            const uint32_t wb = sb + (pg ? SM_W1 : SM_W0);
            const uint32_t xb = sb + (pg ? SM_X1 : SM_X0);
            MBAR_EXPECT_TX(fb, STAGE_BYTES);
            #pragma unroll
            for (int ch = 0; ch < 4; ch++) {
                const int kc = g * GRP_K + ch * 32;
                TMA_LOAD_2D(wb + ch * 16384, &w_map, kc, nt * N_TILE, fb);
                TMA_LOAD_2D(xb + ch * 8192,  &x_map, kc, 0,           fb);
            }
        }
    }

    // 16 warps: khalf = wid>>3 picks K-half; within half: wm 0..3, wn 0..1
    const int khalf = wid >> 3;
    const int wrem  = wid & 7;
    const int wm = wrem & 3;
    const int wn = wrem >> 2;
    const int lane7 = lane & 7;
    const uint32_t sw = (uint32_t)lane7 << 4;               // SW128 XOR
    const uint32_t hA = (uint32_t)((lane >> 4) & 1) * 16u;  // A k-sub per thread
    const uint32_t hB = (uint32_t)((lane >> 3) & 1) * 16u;  // B k-sub per thread
    const int rowA = wm * 32 + ((lane >> 3) & 1) * 8 + lane7;
    const int tokB = wn * 32 + ((lane >> 4) & 1) * 8 + lane7;
    const uint32_t aRow0 = (uint32_t)rowA * 128u;
    const uint32_t aRow1 = (uint32_t)(rowA + 16) * 128u;
    const uint32_t bRow0 = (uint32_t)tokB * 128u;
    const uint32_t bRow1 = (uint32_t)(tokB + 16) * 128u;
    const int rr = wm * 32 + (lane >> 2);                   // fragment base row

    float acc[2][4][4];
    #pragma unroll
    for (int mt = 0; mt < 2; mt++)
        #pragma unroll
        for (int ntl = 0; ntl < 4; ntl++)
            #pragma unroll
            for (int i = 0; i < 4; i++) acc[mt][ntl][i] = 0.0f;

    for (int s = 0; s < nu; s++) {
        const int u  = u0 + s;
        const int nt = u >> 5;
        const int g  = u & 31;
        const int b  = s & 1;
        const int ph = (s >> 1) & 1;
        const uint32_t fb  = b ? full1  : full0;
        const uint32_t eb  = b ? empty1 : empty0;
        const uint32_t wbase = sb + (b ? SM_W1 : SM_W0);
        const uint32_t xbase = sb + (b ? SM_X1 : SM_X0);
        const int n0c = nt * N_TILE;

        // per-group scales (4 rows per thread) — issued before the wait
        const float s00 = wscale[(size_t)(n0c + rr)      * NGRP + g];
        const float s01 = wscale[(size_t)(n0c + rr + 8)  * NGRP + g];
        const float s10 = wscale[(size_t)(n0c + rr + 16) * NGRP + g];
        const float s11 = wscale[(size_t)(n0c + rr + 24) * NGRP + g];

        MBAR_WAIT(fb, ph);

        #pragma unroll
        for (int kk = 0; kk < 8; kk++) {
            const int kkg = khalf * 8 + kk;
            const uint32_t ch16 = (uint32_t)(kkg >> 2) * 16384u;
            const uint32_t ch8  = (uint32_t)(kkg >> 2) * 8192u;
            const uint32_t cbk  = (uint32_t)(kkg & 3) * 32u;
            const uint32_t offA = (cbk + hA) ^ sw;
            const uint32_t offB = (cbk + hB) ^ sw;

            uint32_t afr0[4], afr1[4], bfr0[4], bfr1[4];
            LDSM_X4(afr0, wbase + ch16 + aRow0 + offA);
            LDSM_X4(afr1, wbase + ch16 + aRow1 + offA);
            LDSM_X4(bfr0, xbase + ch8  + bRow0 + offB);
            LDSM_X4(bfr1, xbase + ch8  + bRow1 + offB);

            // pre-scale A fragments (regs a0/a2 -> row rr(+16), a1/a3 -> row rr+8(+24))
            float fa0[4], fa1[4];
            fa0[0] = __uint_as_float(afr0[0]) * s00;
            fa0[1] = __uint_as_float(afr0[1]) * s01;
            fa0[2] = __uint_as_float(afr0[2]) * s00;
            fa0[3] = __uint_as_float(afr0[3]) * s01;
            fa1[0] = __uint_as_float(afr1[0]) * s10;
            fa1[1] = __uint_as_float(afr1[1]) * s11;
            fa1[2] = __uint_as_float(afr1[2]) * s10;
            fa1[3] = __uint_as_float(afr1[3]) * s11;

            mma_tf32f(acc[0][0], fa0, bfr0[0], bfr0[1]);
            mma_tf32f(acc[0][1], fa0, bfr0[2], bfr0[3]);
            mma_tf32f(acc[0][2], fa0, bfr1[0], bfr1[1]);
            mma_tf32f(acc[0][3], fa0, bfr1[2], bfr1[3]);
            mma_tf32f(acc[1][0], fa1, bfr0[0], bfr0[1]);
            mma_tf32f(acc[1][1], fa1, bfr0[2], bfr0[3]);
            mma_tf32f(acc[1][2], fa1, bfr1[0], bfr1[1]);
            mma_tf32f(acc[1][3], fa1, bfr1[2], bfr1[3]);
        }

        MBAR_ARRIVE(eb);

        // Refill this buffer with stage s+2
        if (tid == 0 && s + 2 < nu) {
            MBAR_WAIT(eb, ph);          // all consumers done with buffer b
            MBAR_EXPECT_TX(fb, STAGE_BYTES);
            const int u2  = u0 + s + 2;
            const int nt2 = u2 >> 5, g2 = u2 & 31;
            #pragma unroll
            for (int ch = 0; ch < 4; ch++) {
                const int kc = g2 * GRP_K + ch * 32;
                TMA_LOAD_2D(wbase + ch * 16384, &w_map, kc, nt2 * N_TILE, fb);
                TMA_LOAD_2D(xbase + ch * 8192,  &x_map, kc, 0,            fb);
            }
        }

        // Flush accumulators at n-tile boundary or end of range
        const bool last = (s == nu - 1);
        if (last || (((u + 1) >> 5) != nt)) {
            // Bias added exactly once: CTA owning g=0 of this tile, khalf 0 only.
            if (khalf == 0 && nt * NGRP >= u0) {
                const float b00 = bias[n0c + rr];
                const float b01 = bias[n0c + rr + 8];
                const float b10 = bias[n0c + rr + 16];
                const float b11 = bias[n0c + rr + 24];
                #pragma unroll
                for (int ntl = 0; ntl < 4; ntl++) {
                    acc[0][ntl][0] += b00; acc[0][ntl][1] += b00;
                    acc[0][ntl][2] += b01; acc[0][ntl][3] += b01;
                    acc[1][ntl][0] += b10; acc[1][ntl][1] += b10;
                    acc[1][ntl][2] += b11; acc[1][ntl][3] += b11;
                }
            }
            #pragma unroll
            for (int mt = 0; mt < 2; mt++) {
                #pragma unroll
                for (int ntl = 0; ntl < 4; ntl++) {
                    #pragma unroll
                    for (int i = 0; i < 4; i++) {
                        const int row_out = n0c + wm * 32 + mt * 16 + (lane >> 2) + ((i >= 2) ? 8 : 0);
                        const int tok     = wn * 32 + ntl * 8 + (lane & 3) * 2 + (i & 1);
                        atomicAdd(&out[(size_t)tok * N_DIM + row_out], acc[mt][ntl][i]);
                        acc[mt][ntl][i] = 0.0f;
                    }
                }
            }
        }
    }
}

// ---------------- host launch ----------------
typedef CUresult (*tmap_encode_fn)(
    CUtensorMap*, CUtensorMapDataType, cuuint32_t, void*,
    const cuuint64_t*, const cuuint64_t*, const cuuint32_t*, const cuuint32_t*,
    CUtensorMapInterleave, CUtensorMapSwizzle, CUtensorMapL2promotion, CUtensorMapFloatOOBfill);

extern "C" void kernel_launch(void* const* d_in, const int* in_sizes, int n_in,
                              void* d_out, int out_size)
{
    const float* x  = (const float*)d_in[0];
    void*        w  = (void*)d_in[1];
    const float* ws = (const float*)d_in[2];
    const float* bs = (const float*)d_in[3];
    float* out = (float*)d_out;

    void* fp = nullptr;
    cudaDriverEntryPointQueryResult qres;
    cudaGetDriverEntryPointByVersion("cuTensorMapEncodeTiled", &fp, 12000,
                                     cudaEnableDefault, &qres);
    if (!fp || qres != cudaDriverEntryPointSuccess) return;
    tmap_encode_fn enc = (tmap_encode_fn)fp;

    void* xr_ptr = nullptr;
    cudaGetSymbolAddress(&xr_ptr, g_x_r);

    CUtensorMap w_map, x_map;
    {
        cuuint64_t dims[2]  = {K_DIM, N_DIM};
        cuuint64_t strd[1]  = {K_DIM * 4};
        cuuint32_t box[2]   = {32, 128};
        cuuint32_t estr[2]  = {1, 1};
        enc(&w_map, CU_TENSOR_MAP_DATA_TYPE_FLOAT32, 2, w, dims, strd, box, estr,
            CU_TENSOR_MAP_INTERLEAVE_NONE, CU_TENSOR_MAP_SWIZZLE_128B,
            CU_TENSOR_MAP_L2_PROMOTION_L2_128B, CU_TENSOR_MAP_FLOAT_OOB_FILL_NONE);
    }
    {
        cuuint64_t dims[2]  = {K_DIM, M_TOK};
        cuuint64_t strd[1]  = {K_DIM * 4};
        cuuint32_t box[2]   = {32, 64};
        cuuint32_t estr[2]  = {1, 1};
        enc(&x_map, CU_TENSOR_MAP_DATA_TYPE_FLOAT32, 2, xr_ptr, dims, strd, box, estr,
            CU_TENSOR_MAP_INTERLEAVE_NONE, CU_TENSOR_MAP_SWIZZLE_128B,
            CU_TENSOR_MAP_L2_PROMOTION_L2_128B, CU_TENSOR_MAP_FLOAT_OOB_FILL_NONE);
    }

    cudaFuncSetAttribute(qlin_kernel, cudaFuncAttributeMaxDynamicSharedMemorySize, SM_TOTAL);

    const int prep_threads = X4_CNT + O4_CNT;           // 241664
    prep_kernel<<<(prep_threads + 255) / 256, 256>>>((const float4*)x, (float4*)out);
    qlin_kernel<<<NUM_CTAS, THREADS, SM_TOTAL>>>(ws, bs, out, w_map, x_map);
}

// round 7
// speedup vs baseline: 1.0529x; 1.0529x over previous
#include <cuda_runtime.h>
#include <cuda.h>
#include <cstdint>

// Problem constants
#define M_TOK   64
#define K_DIM   4096
#define N_DIM   11008
#define NGRP    32           // K groups of 128
#define GRP_K   128
#define N_TILE  128
#define NUM_NT  (N_DIM / N_TILE)          // 86
#define U_TOTAL (NUM_NT * NGRP)           // 2752 group-units
#define NUM_CTAS 148
#define THREADS 256

// Pipeline: 4 stages, each covering 64 K-columns (half a scale group)
#define STAGE_K      64
#define STAGE_W_B    (N_TILE * STAGE_K * 4)   // 32768
#define STAGE_X_B    (M_TOK  * STAGE_K * 4)   // 16384
#define STAGE_BYTES  (STAGE_W_B + STAGE_X_B)  // 49152
#define NSTAGE 4

// SMEM layout
#define SM_MBAR   0           // full[0..3] at +0..24, empty[0..3] at +32..56
#define SM_TILES  1024
#define SM_TOTAL  (SM_TILES + NSTAGE * STAGE_BYTES)   // 197632

// scratch: x pre-rounded to nearest-tf32 (stored as f32 bit patterns)
__device__ __align__(1024) float g_x_r[M_TOK * K_DIM];

// ---------------- PTX helpers ----------------
static __device__ __forceinline__ uint32_t smem_u32(const void* p) {
    uint32_t a;
    asm("{ .reg .u64 t; cvta.to.shared.u64 t, %1; cvt.u32.u64 %0, t; }" : "=r"(a) : "l"(p));
    return a;
}

#define MBAR_INIT(addr, cnt) \
    asm volatile("mbarrier.init.shared.b64 [%0], %1;" :: "r"(addr), "r"((uint32_t)(cnt)) : "memory")

#define MBAR_EXPECT_TX(addr, bytes) \
    asm volatile("mbarrier.arrive.expect_tx.shared.b64 _, [%0], %1;" :: "r"(addr), "r"((uint32_t)(bytes)) : "memory")

#define MBAR_ARRIVE(addr) \
    asm volatile("mbarrier.arrive.shared.b64 _, [%0];" :: "r"(addr) : "memory")

#define MBAR_WAIT(addr, parity) do {                                              \
    uint32_t _mb = (addr); uint32_t _ph = (parity); uint32_t _done;               \
    asm volatile("{\n\t.reg .pred p;\n\t"                                         \
        "mbarrier.try_wait.parity.shared::cta.b64 p, [%1], %2;\n\t"               \
        "selp.b32 %0, 1, 0, p;\n\t}"                                              \
        : "=r"(_done) : "r"(_mb), "r"(_ph) : "memory");                           \
    if (!_done) {                                                                 \
        asm volatile("{\n\t.reg .pred P1;\n\t"                                    \
        "WL_%=:\n\t"                                                              \
        "mbarrier.try_wait.parity.shared::cta.b64 P1, [%0], %1, 0x989680;\n\t"    \
        "@P1 bra.uni WD_%=;\n\t"                                                  \
        "bra.uni WL_%=;\n\t"                                                      \
        "WD_%=:\n\t}" :: "r"(_mb), "r"(_ph) : "memory");                          \
    }                                                                             \
} while (0)

#define TMA_LOAD_2D(sdst, map, cx, cy, mbar) \
    asm volatile("cp.async.bulk.tensor.2d.shared::cta.global.tile.mbarrier::complete_tx::bytes " \
                 "[%0], [%1, {%2, %3}], [%4];" \
                 :: "r"(sdst), "l"(map), "r"(cx), "r"(cy), "r"(mbar) : "memory")

#define LDSM_X4(R, addr) \
    asm volatile("ldmatrix.sync.aligned.m8n8.x4.shared.b16 {%0,%1,%2,%3}, [%4];" \
        : "=r"((R)[0]), "=r"((R)[1]), "=r"((R)[2]), "=r"((R)[3]) : "r"(addr))

// m16n8k8 tf32 MMA, D += A*B (uint fragments)
static __device__ __forceinline__ void mma_tf32u(
    float* d, const uint32_t* a, uint32_t b0, uint32_t b1)
{
    asm volatile(
        "mma.sync.aligned.m16n8k8.row.col.f32.tf32.tf32.f32 "
        "{%0,%1,%2,%3}, {%4,%5,%6,%7}, {%8,%9}, {%0,%1,%2,%3};"
        : "+f"(d[0]), "+f"(d[1]), "+f"(d[2]), "+f"(d[3])
        : "r"(a[0]), "r"(a[1]), "r"(a[2]), "r"(a[3]), "r"(b0), "r"(b1));
}

// ---------------- prologue: round x to nearest-tf32 ----------------
#define X4_CNT  (M_TOK * K_DIM / 4)      // 65536

__global__ void prep_kernel(const float4* __restrict__ x4)
{
    int i = blockIdx.x * blockDim.x + threadIdx.x;
    if (i < X4_CNT) {
        float4 v = x4[i];
        uint32_t r0, r1, r2, r3;
        asm("cvt.rna.tf32.f32 %0, %1;" : "=r"(r0) : "f"(v.x));
        asm("cvt.rna.tf32.f32 %0, %1;" : "=r"(r1) : "f"(v.y));
        asm("cvt.rna.tf32.f32 %0, %1;" : "=r"(r2) : "f"(v.z));
        asm("cvt.rna.tf32.f32 %0, %1;" : "=r"(r3) : "f"(v.w));
        float4 o;
        o.x = __uint_as_float(r0); o.y = __uint_as_float(r1);
        o.z = __uint_as_float(r2); o.w = __uint_as_float(r3);
        ((float4*)g_x_r)[i] = o;
    }
}

// ---------------- main kernel (persistent, 4-stage pipeline, LDSM) ----------------
__global__ void __launch_bounds__(THREADS, 1) qlin_kernel(
    const float* __restrict__ wscale,
    const float* __restrict__ bias,
    float* __restrict__ out,
    const __grid_constant__ CUtensorMap w_map,
    const __grid_constant__ CUtensorMap x_map)
{
    extern __shared__ char smem[];
    const uint32_t sb = smem_u32(smem);
    const int tid  = threadIdx.x;
    const int wid  = tid >> 5;
    const int lane = tid & 31;

    // Balanced contiguous range of group-units over flattened (nt, g)
    const int c  = blockIdx.x;
    const int u0 = (int)(((long long)c       * U_TOTAL) / NUM_CTAS);
    const int u1 = (int)(((long long)(c + 1) * U_TOTAL) / NUM_CTAS);
    const int nu = u1 - u0;                 // 18 or 19
    const int nstages_tot = nu * 2;         // 64-K stages

    if (tid == 0) {
        #pragma unroll
        for (int i = 0; i < NSTAGE; i++) {
            MBAR_INIT(sb + SM_MBAR + i * 8,      1);        // full[i]
            MBAR_INIT(sb + SM_MBAR + 32 + i * 8, THREADS);  // empty[i]
        }
    }
    __syncthreads();

    // Prologue: issue stages 0..3 (nstages_tot >= 36 always)
    if (tid == 0) {
        #pragma unroll
        for (int t = 0; t < NSTAGE; t++) {
            const int u  = u0 + (t >> 1);
            const int nt = u >> 5, g = u & 31, hh = t & 1;
            const uint32_t fb = sb + SM_MBAR + t * 8;
            const uint32_t wb = sb + SM_TILES + t * STAGE_BYTES;
            const uint32_t xb = wb + STAGE_W_B;
            MBAR_EXPECT_TX(fb, STAGE_BYTES);
            const int kc = g * GRP_K + hh * STAGE_K;
            TMA_LOAD_2D(wb,          &w_map, kc,      nt * N_TILE, fb);
            TMA_LOAD_2D(wb + 16384,  &w_map, kc + 32, nt * N_TILE, fb);
            TMA_LOAD_2D(xb,          &x_map, kc,      0,           fb);
            TMA_LOAD_2D(xb + 8192,   &x_map, kc + 32, 0,           fb);
        }
    }

    // Warp tiling (8 warps): rows [wm*32,+32), tokens [wn*32,+32)
    const int wm = wid & 3;
    const int wn = wid >> 2;
    const int lane7 = lane & 7;
    const uint32_t sw = (uint32_t)lane7 << 4;               // SW128 XOR
    const uint32_t hA = (uint32_t)((lane >> 4) & 1) * 16u;  // A k-sub
    const uint32_t hB = (uint32_t)((lane >> 3) & 1) * 16u;  // B k-sub
    const int rowA = wm * 32 + ((lane >> 3) & 1) * 8 + lane7;
    const int tokB = wn * 32 + ((lane >> 4) & 1) * 8 + lane7;
    const uint32_t aRow0 = (uint32_t)rowA * 128u;
    const uint32_t aRow1 = (uint32_t)(rowA + 16) * 128u;
    const uint32_t bRow0 = (uint32_t)tokB * 128u;
    const uint32_t bRow1 = (uint32_t)(tokB + 16) * 128u;
    const int rr = wm * 32 + (lane >> 2);                   // fragment base row

    float acc[2][4][4];
    #pragma unroll
    for (int mt = 0; mt < 2; mt++)
        #pragma unroll
        for (int ntl = 0; ntl < 4; ntl++)
            #pragma unroll
            for (int i = 0; i < 4; i++) acc[mt][ntl][i] = 0.0f;

    for (int s = 0; s < nu; s++) {
        const int u  = u0 + s;
        const int nt = u >> 5;
        const int g  = u & 31;
        const int n0c = nt * N_TILE;

        // per-group scales (4 rows per thread) — issued before the waits
        const float s00 = wscale[(size_t)(n0c + rr)      * NGRP + g];
        const float s01 = wscale[(size_t)(n0c + rr + 8)  * NGRP + g];
        const float s10 = wscale[(size_t)(n0c + rr + 16) * NGRP + g];
        const float s11 = wscale[(size_t)(n0c + rr + 24) * NGRP + g];

        float gacc[2][4][4];
        #pragma unroll
        for (int mt = 0; mt < 2; mt++)
            #pragma unroll
            for (int ntl = 0; ntl < 4; ntl++)
                #pragma unroll
                for (int i = 0; i < 4; i++) gacc[mt][ntl][i] = 0.0f;

        #pragma unroll
        for (int hh = 0; hh < 2; hh++) {
            const int t   = 2 * s + hh;
            const int buf = t & 3;
            const int ph  = (t >> 2) & 1;
            const uint32_t fb = sb + SM_MBAR + buf * 8;
            const uint32_t eb = sb + SM_MBAR + 32 + buf * 8;
            const uint32_t wbase = sb + SM_TILES + buf * STAGE_BYTES;
            const uint32_t xbase = wbase + STAGE_W_B;

            MBAR_WAIT(fb, ph);

            #pragma unroll
            for (int kk = 0; kk < 8; kk++) {
                const uint32_t ch16 = (uint32_t)(kk >> 2) * 16384u;
                const uint32_t ch8  = (uint32_t)(kk >> 2) * 8192u;
                const uint32_t cbk  = (uint32_t)(kk & 3) * 32u;
                const uint32_t offA = (cbk + hA) ^ sw;
                const uint32_t offB = (cbk + hB) ^ sw;

                uint32_t afr0[4], afr1[4], bfr0[4], bfr1[4];
                LDSM_X4(afr0, wbase + ch16 + aRow0 + offA);
                LDSM_X4(afr1, wbase + ch16 + aRow1 + offA);
                LDSM_X4(bfr0, xbase + ch8  + bRow0 + offB);
                LDSM_X4(bfr1, xbase + ch8  + bRow1 + offB);

                mma_tf32u(gacc[0][0], afr0, bfr0[0], bfr0[1]);
                mma_tf32u(gacc[0][1], afr0, bfr0[2], bfr0[3]);
                mma_tf32u(gacc[0][2], afr0, bfr1[0], bfr1[1]);
                mma_tf32u(gacc[0][3], afr0, bfr1[2], bfr1[3]);
                mma_tf32u(gacc[1][0], afr1, bfr0[0], bfr0[1]);
                mma_tf32u(gacc[1][1], afr1, bfr0[2], bfr0[3]);
                mma_tf32u(gacc[1][2], afr1, bfr1[0], bfr1[1]);
                mma_tf32u(gacc[1][3], afr1, bfr1[2], bfr1[3]);
            }

            MBAR_ARRIVE(eb);

            // Refill buffer `buf` with stage t+4 (3 stages of slack)
            if (tid == 0 && t + 4 < nstages_tot) {
                MBAR_WAIT(eb, ph);          // all consumers done with this buffer
                MBAR_EXPECT_TX(fb, STAGE_BYTES);
                const int t2  = t + 4;
                const int u2  = u0 + (t2 >> 1);
                const int nt2 = u2 >> 5, g2 = u2 & 31, hh2 = t2 & 1;
                const int kc = g2 * GRP_K + hh2 * STAGE_K;
                TMA_LOAD_2D(wbase,         &w_map, kc,      nt2 * N_TILE, fb);
                TMA_LOAD_2D(wbase + 16384, &w_map, kc + 32, nt2 * N_TILE, fb);
                TMA_LOAD_2D(xbase,         &x_map, kc,      0,            fb);
                TMA_LOAD_2D(xbase + 8192,  &x_map, kc + 32, 0,            fb);
            }
        }

        // fold group into master accumulators with per-row scale
        #pragma unroll
        for (int ntl = 0; ntl < 4; ntl++) {
            acc[0][ntl][0] = fmaf(s00, gacc[0][ntl][0], acc[0][ntl][0]);
            acc[0][ntl][1] = fmaf(s00, gacc[0][ntl][1], acc[0][ntl][1]);
            acc[0][ntl][2] = fmaf(s01, gacc[0][ntl][2], acc[0][ntl][2]);
            acc[0][ntl][3] = fmaf(s01, gacc[0][ntl][3], acc[0][ntl][3]);
            acc[1][ntl][0] = fmaf(s10, gacc[1][ntl][0], acc[1][ntl][0]);
            acc[1][ntl][1] = fmaf(s10, gacc[1][ntl][1], acc[1][ntl][1]);
            acc[1][ntl][2] = fmaf(s11, gacc[1][ntl][2], acc[1][ntl][2]);
            acc[1][ntl][3] = fmaf(s11, gacc[1][ntl][3], acc[1][ntl][3]);
        }

        // Flush accumulators at n-tile boundary or end of range
        const bool last = (s == nu - 1);
        if (last || (((u + 1) >> 5) != nt)) {
            // Bias added exactly once: the CTA owning g=0 of this tile.
            if (nt * NGRP >= u0) {
                const float b00 = bias[n0c + rr];
                const float b01 = bias[n0c + rr + 8];
                const float b10 = bias[n0c + rr + 16];
                const float b11 = bias[n0c + rr + 24];
                #pragma unroll
                for (int ntl = 0; ntl < 4; ntl++) {
                    acc[0][ntl][0] += b00; acc[0][ntl][1] += b00;
                    acc[0][ntl][2] += b01; acc[0][ntl][3] += b01;
                    acc[1][ntl][0] += b10; acc[1][ntl][1] += b10;
                    acc[1][ntl][2] += b11; acc[1][ntl][3] += b11;
                }
            }
            #pragma unroll
            for (int mt = 0; mt < 2; mt++) {
                #pragma unroll
                for (int ntl = 0; ntl < 4; ntl++) {
                    #pragma unroll
                    for (int i = 0; i < 4; i++) {
                        const int row_out = n0c + wm * 32 + mt * 16 + (lane >> 2) + ((i >= 2) ? 8 : 0);
                        const int tok     = wn * 32 + ntl * 8 + (lane & 3) * 2 + (i & 1);
                        atomicAdd(&out[(size_t)tok * N_DIM + row_out], acc[mt][ntl][i]);
                        acc[mt][ntl][i] = 0.0f;
                    }
                }
            }
        }
    }
}

// ---------------- host launch ----------------
typedef CUresult (*tmap_encode_fn)(
    CUtensorMap*, CUtensorMapDataType, cuuint32_t, void*,
    const cuuint64_t*, const cuuint64_t*, const cuuint32_t*, const cuuint32_t*,
    CUtensorMapInterleave, CUtensorMapSwizzle, CUtensorMapL2promotion, CUtensorMapFloatOOBfill);

extern "C" void kernel_launch(void* const* d_in, const int* in_sizes, int n_in,
                              void* d_out, int out_size)
{
    const float* x  = (const float*)d_in[0];
    void*        w  = (void*)d_in[1];
    const float* ws = (const float*)d_in[2];
    const float* bs = (const float*)d_in[3];
    float* out = (float*)d_out;

    void* fp = nullptr;
    cudaDriverEntryPointQueryResult qres;
    cudaGetDriverEntryPointByVersion("cuTensorMapEncodeTiled", &fp, 12000,
                                     cudaEnableDefault, &qres);
    if (!fp || qres != cudaDriverEntryPointSuccess) return;
    tmap_encode_fn enc = (tmap_encode_fn)fp;

    void* xr_ptr = nullptr;
    cudaGetSymbolAddress(&xr_ptr, g_x_r);

    CUtensorMap w_map, x_map;
    {
        cuuint64_t dims[2]  = {K_DIM, N_DIM};
        cuuint64_t strd[1]  = {K_DIM * 4};
        cuuint32_t box[2]   = {32, 128};
        cuuint32_t estr[2]  = {1, 1};
        enc(&w_map, CU_TENSOR_MAP_DATA_TYPE_FLOAT32, 2, w, dims, strd, box, estr,
            CU_TENSOR_MAP_INTERLEAVE_NONE, CU_TENSOR_MAP_SWIZZLE_128B,
            CU_TENSOR_MAP_L2_PROMOTION_L2_128B, CU_TENSOR_MAP_FLOAT_OOB_FILL_NONE);
    }
    {
        cuuint64_t dims[2]  = {K_DIM, M_TOK};
        cuuint64_t strd[1]  = {K_DIM * 4};
        cuuint32_t box[2]   = {32, 64};
        cuuint32_t estr[2]  = {1, 1};
        enc(&x_map, CU_TENSOR_MAP_DATA_TYPE_FLOAT32, 2, xr_ptr, dims, strd, box, estr,
            CU_TENSOR_MAP_INTERLEAVE_NONE, CU_TENSOR_MAP_SWIZZLE_128B,
            CU_TENSOR_MAP_L2_PROMOTION_L2_128B, CU_TENSOR_MAP_FLOAT_OOB_FILL_NONE);
    }

    cudaFuncSetAttribute(qlin_kernel, cudaFuncAttributeMaxDynamicSharedMemorySize, SM_TOTAL);

    cudaMemsetAsync(out, 0, (size_t)M_TOK * N_DIM * sizeof(float));
    prep_kernel<<<(X4_CNT + 255) / 256, 256>>>((const float4*)x);
    qlin_kernel<<<NUM_CTAS, THREADS, SM_TOTAL>>>(ws, bs, out, w_map, x_map);
}

// round 8
// speedup vs baseline: 1.0623x; 1.0089x over previous
#include <cuda_runtime.h>
#include <cuda.h>
#include <cstdint>

// Problem constants
#define M_TOK   64
#define K_DIM   4096
#define N_DIM   11008
#define NGRP    32           // K groups of 128
#define GRP_K   128
#define N_TILE  128
#define NUM_NT  (N_DIM / N_TILE)          // 86
#define U_TOTAL (NUM_NT * NGRP)           // 2752 group-units
#define NUM_CTAS 148
#define THREADS 256

// Pipeline: 4 stages, each covering 64 K-columns (half a scale group)
#define STAGE_K      64
#define STAGE_W_B    (N_TILE * STAGE_K * 4)   // 32768
#define STAGE_X_B    (M_TOK  * STAGE_K * 4)   // 16384
#define STAGE_BYTES  (STAGE_W_B + STAGE_X_B)  // 49152
#define NSTAGE 4

// SMEM layout
#define SM_MBAR   0           // full[0..3] at +0..24, empty[0..3] at +32..56
#define SM_TILES  1024
#define SM_TOTAL  (SM_TILES + NSTAGE * STAGE_BYTES)   // 197632

// scratch: x pre-rounded to nearest-tf32 (stored as f32 bit patterns)
__device__ __align__(1024) float g_x_r[M_TOK * K_DIM];

// ---------------- PTX helpers ----------------
static __device__ __forceinline__ uint32_t smem_u32(const void* p) {
    uint32_t a;
    asm("{ .reg .u64 t; cvta.to.shared.u64 t, %1; cvt.u32.u64 %0, t; }" : "=r"(a) : "l"(p));
    return a;
}

#define MBAR_INIT(addr, cnt) \
    asm volatile("mbarrier.init.shared.b64 [%0], %1;" :: "r"(addr), "r"((uint32_t)(cnt)) : "memory")

#define MBAR_EXPECT_TX(addr, bytes) \
    asm volatile("mbarrier.arrive.expect_tx.shared.b64 _, [%0], %1;" :: "r"(addr), "r"((uint32_t)(bytes)) : "memory")

#define MBAR_ARRIVE(addr) \
    asm volatile("mbarrier.arrive.shared.b64 _, [%0];" :: "r"(addr) : "memory")

#define MBAR_WAIT(addr, parity) do {                                              \
    uint32_t _mb = (addr); uint32_t _ph = (parity); uint32_t _done;               \
    asm volatile("{\n\t.reg .pred p;\n\t"                                         \
        "mbarrier.try_wait.parity.shared::cta.b64 p, [%1], %2;\n\t"               \
        "selp.b32 %0, 1, 0, p;\n\t}"                                              \
        : "=r"(_done) : "r"(_mb), "r"(_ph) : "memory");                           \
    if (!_done) {                                                                 \
        asm volatile("{\n\t.reg .pred P1;\n\t"                                    \
        "WL_%=:\n\t"                                                              \
        "mbarrier.try_wait.parity.shared::cta.b64 P1, [%0], %1, 0x989680;\n\t"    \
        "@P1 bra.uni WD_%=;\n\t"                                                  \
        "bra.uni WL_%=;\n\t"                                                      \
        "WD_%=:\n\t}" :: "r"(_mb), "r"(_ph) : "memory");                          \
    }                                                                             \
} while (0)

#define TMA_LOAD_2D(sdst, map, cx, cy, mbar) \
    asm volatile("cp.async.bulk.tensor.2d.shared::cta.global.tile.mbarrier::complete_tx::bytes " \
                 "[%0], [%1, {%2, %3}], [%4];" \
                 :: "r"(sdst), "l"(map), "r"(cx), "r"(cy), "r"(mbar) : "memory")

#define LDSM_X4(R, addr) \
    asm volatile("ldmatrix.sync.aligned.m8n8.x4.shared.b16 {%0,%1,%2,%3}, [%4];" \
        : "=r"((R)[0]), "=r"((R)[1]), "=r"((R)[2]), "=r"((R)[3]) : "r"(addr))

// m16n8k8 tf32 MMA, D += A*B (uint fragments)
static __device__ __forceinline__ void mma_tf32u(
    float* d, const uint32_t* a, uint32_t b0, uint32_t b1)
{
    asm volatile(
        "mma.sync.aligned.m16n8k8.row.col.f32.tf32.tf32.f32 "
        "{%0,%1,%2,%3}, {%4,%5,%6,%7}, {%8,%9}, {%0,%1,%2,%3};"
        : "+f"(d[0]), "+f"(d[1]), "+f"(d[2]), "+f"(d[3])
        : "r"(a[0]), "r"(a[1]), "r"(a[2]), "r"(a[3]), "r"(b0), "r"(b1));
}

// ---------------- prologue: round x to nearest-tf32 ----------------
#define X4_CNT  (M_TOK * K_DIM / 4)      // 65536

__global__ void prep_kernel(const float4* __restrict__ x4)
{
    int i = blockIdx.x * blockDim.x + threadIdx.x;
    if (i < X4_CNT) {
        float4 v = x4[i];
        uint32_t r0, r1, r2, r3;
        asm("cvt.rna.tf32.f32 %0, %1;" : "=r"(r0) : "f"(v.x));
        asm("cvt.rna.tf32.f32 %0, %1;" : "=r"(r1) : "f"(v.y));
        asm("cvt.rna.tf32.f32 %0, %1;" : "=r"(r2) : "f"(v.z));
        asm("cvt.rna.tf32.f32 %0, %1;" : "=r"(r3) : "f"(v.w));
        float4 o;
        o.x = __uint_as_float(r0); o.y = __uint_as_float(r1);
        o.z = __uint_as_float(r2); o.w = __uint_as_float(r3);
        ((float4*)g_x_r)[i] = o;
    }
}

// ---------------- main kernel (persistent, 4-stage TMA, SW-pipelined LDSM) ----------------
__global__ void __launch_bounds__(THREADS, 1) qlin_kernel(
    const float* __restrict__ wscale,
    const float* __restrict__ bias,
    float* __restrict__ out,
    const __grid_constant__ CUtensorMap w_map,
    const __grid_constant__ CUtensorMap x_map)
{
    extern __shared__ char smem[];
    const uint32_t sb = smem_u32(smem);
    const int tid  = threadIdx.x;
    const int wid  = tid >> 5;
    const int lane = tid & 31;

    // Balanced contiguous range of group-units over flattened (nt, g)
    const int c  = blockIdx.x;
    const int u0 = (int)(((long long)c       * U_TOTAL) / NUM_CTAS);
    const int u1 = (int)(((long long)(c + 1) * U_TOTAL) / NUM_CTAS);
    const int nu = u1 - u0;                 // 18 or 19
    const int nstages_tot = nu * 2;         // 64-K stages

    if (tid == 0) {
        #pragma unroll
        for (int i = 0; i < NSTAGE; i++) {
            MBAR_INIT(sb + SM_MBAR + i * 8,      1);        // full[i]
            MBAR_INIT(sb + SM_MBAR + 32 + i * 8, THREADS);  // empty[i]
        }
    }
    __syncthreads();

    // Prologue: issue stages 0..3
    if (tid == 0) {
        #pragma unroll
        for (int t = 0; t < NSTAGE; t++) {
            const int u  = u0 + (t >> 1);
            const int nt = u >> 5, g = u & 31, hh = t & 1;
            const uint32_t fb = sb + SM_MBAR + t * 8;
            const uint32_t wb = sb + SM_TILES + t * STAGE_BYTES;
            const uint32_t xb = wb + STAGE_W_B;
            MBAR_EXPECT_TX(fb, STAGE_BYTES);
            const int kc = g * GRP_K + hh * STAGE_K;
            TMA_LOAD_2D(wb,          &w_map, kc,      nt * N_TILE, fb);
            TMA_LOAD_2D(wb + 16384,  &w_map, kc + 32, nt * N_TILE, fb);
            TMA_LOAD_2D(xb,          &x_map, kc,      0,           fb);
            TMA_LOAD_2D(xb + 8192,   &x_map, kc + 32, 0,           fb);
        }
    }

    // Warp tiling (8 warps): rows [wm*32,+32), tokens [wn*32,+32)
    const int wm = wid & 3;
    const int wn = wid >> 2;
    const int lane7 = lane & 7;
    const uint32_t sw = (uint32_t)lane7 << 4;               // SW128 XOR
    const uint32_t hA = (uint32_t)((lane >> 4) & 1) * 16u;  // A k-sub
    const uint32_t hB = (uint32_t)((lane >> 3) & 1) * 16u;  // B k-sub
    const int rowA = wm * 32 + ((lane >> 3) & 1) * 8 + lane7;
    const int tokB = wn * 32 + ((lane >> 4) & 1) * 8 + lane7;
    const uint32_t aRow0 = (uint32_t)rowA * 128u;
    const uint32_t aRow1 = (uint32_t)(rowA + 16) * 128u;
    const uint32_t bRow0 = (uint32_t)tokB * 128u;
    const uint32_t bRow1 = (uint32_t)(tokB + 16) * 128u;
    const int rr = wm * 32 + (lane >> 2);                   // fragment base row

    float acc[2][4][4];
    #pragma unroll
    for (int mt = 0; mt < 2; mt++)
        #pragma unroll
        for (int ntl = 0; ntl < 4; ntl++)
            #pragma unroll
            for (int i = 0; i < 4; i++) acc[mt][ntl][i] = 0.0f;

    for (int s = 0; s < nu; s++) {
        const int u  = u0 + s;
        const int nt = u >> 5;
        const int g  = u & 31;
        const int n0c = nt * N_TILE;

        // per-group scales (4 rows per thread) — issued before the waits
        const float s00 = wscale[(size_t)(n0c + rr)      * NGRP + g];
        const float s01 = wscale[(size_t)(n0c + rr + 8)  * NGRP + g];
        const float s10 = wscale[(size_t)(n0c + rr + 16) * NGRP + g];
        const float s11 = wscale[(size_t)(n0c + rr + 24) * NGRP + g];

        float gacc[2][4][4];
        #pragma unroll
        for (int mt = 0; mt < 2; mt++)
            #pragma unroll
            for (int ntl = 0; ntl < 4; ntl++)
                #pragma unroll
                for (int i = 0; i < 4; i++) gacc[mt][ntl][i] = 0.0f;

        #pragma unroll
        for (int hh = 0; hh < 2; hh++) {
            const int t   = 2 * s + hh;
            const int buf = t & 3;
            const int ph  = (t >> 2) & 1;
            const uint32_t fb = sb + SM_MBAR + buf * 8;
            const uint32_t eb = sb + SM_MBAR + 32 + buf * 8;
            const uint32_t wbase = sb + SM_TILES + buf * STAGE_BYTES;
            const uint32_t xbase = wbase + STAGE_W_B;

            MBAR_WAIT(fb, ph);

            // Software-pipelined fragment loads: LDSM for kk+1 issued before MMAs of kk.
            uint32_t afr0[2][4], afr1[2][4], bfr0[2][4], bfr1[2][4];

            #define LOAD_FRAGS(pb, kk) do {                                      \
                const uint32_t ch16 = (uint32_t)((kk) >> 2) * 16384u;             \
                const uint32_t ch8  = (uint32_t)((kk) >> 2) * 8192u;              \
                const uint32_t cbk  = (uint32_t)((kk) & 3) * 32u;                 \
                const uint32_t offA = (cbk + hA) ^ sw;                            \
                const uint32_t offB = (cbk + hB) ^ sw;                            \
                LDSM_X4(afr0[pb], wbase + ch16 + aRow0 + offA);                   \
                LDSM_X4(afr1[pb], wbase + ch16 + aRow1 + offA);                   \
                LDSM_X4(bfr0[pb], xbase + ch8  + bRow0 + offB);                   \
                LDSM_X4(bfr1[pb], xbase + ch8  + bRow1 + offB);                   \
            } while (0)

            LOAD_FRAGS(0, 0);
            #pragma unroll
            for (int kk = 0; kk < 8; kk++) {
                const int cur = kk & 1;
                if (kk < 7) LOAD_FRAGS(!cur, kk + 1);
                mma_tf32u(gacc[0][0], afr0[cur], bfr0[cur][0], bfr0[cur][1]);
                mma_tf32u(gacc[0][1], afr0[cur], bfr0[cur][2], bfr0[cur][3]);
                mma_tf32u(gacc[0][2], afr0[cur], bfr1[cur][0], bfr1[cur][1]);
                mma_tf32u(gacc[0][3], afr0[cur], bfr1[cur][2], bfr1[cur][3]);
                mma_tf32u(gacc[1][0], afr1[cur], bfr0[cur][0], bfr0[cur][1]);
                mma_tf32u(gacc[1][1], afr1[cur], bfr0[cur][2], bfr0[cur][3]);
                mma_tf32u(gacc[1][2], afr1[cur], bfr1[cur][0], bfr1[cur][1]);
                mma_tf32u(gacc[1][3], afr1[cur], bfr1[cur][2], bfr1[cur][3]);
            }
            #undef LOAD_FRAGS

            MBAR_ARRIVE(eb);

            // Refill buffer `buf` with stage t+4 (3 stages of slack)
            if (tid == 0 && t + 4 < nstages_tot) {
                MBAR_WAIT(eb, ph);          // all consumers done with this buffer
                MBAR_EXPECT_TX(fb, STAGE_BYTES);
                const int t2  = t + 4;
                const int u2  = u0 + (t2 >> 1);
                const int nt2 = u2 >> 5, g2 = u2 & 31, hh2 = t2 & 1;
                const int kc = g2 * GRP_K + hh2 * STAGE_K;
                TMA_LOAD_2D(wbase,         &w_map, kc,      nt2 * N_TILE, fb);
                TMA_LOAD_2D(wbase + 16384, &w_map, kc + 32, nt2 * N_TILE, fb);
                TMA_LOAD_2D(xbase,         &x_map, kc,      0,            fb);
                TMA_LOAD_2D(xbase + 8192,  &x_map, kc + 32, 0,            fb);
            }
        }

        // fold group into master accumulators with per-row scale
        #pragma unroll
        for (int ntl = 0; ntl < 4; ntl++) {
            acc[0][ntl][0] = fmaf(s00, gacc[0][ntl][0], acc[0][ntl][0]);
            acc[0][ntl][1] = fmaf(s00, gacc[0][ntl][1], acc[0][ntl][1]);
            acc[0][ntl][2] = fmaf(s01, gacc[0][ntl][2], acc[0][ntl][2]);
            acc[0][ntl][3] = fmaf(s01, gacc[0][ntl][3], acc[0][ntl][3]);
            acc[1][ntl][0] = fmaf(s10, gacc[1][ntl][0], acc[1][ntl][0]);
            acc[1][ntl][1] = fmaf(s10, gacc[1][ntl][1], acc[1][ntl][1]);
            acc[1][ntl][2] = fmaf(s11, gacc[1][ntl][2], acc[1][ntl][2]);
            acc[1][ntl][3] = fmaf(s11, gacc[1][ntl][3], acc[1][ntl][3]);
        }

        // Flush accumulators at n-tile boundary or end of range
        const bool last = (s == nu - 1);
        if (last || (((u + 1) >> 5) != nt)) {
            // Bias added exactly once: the CTA owning g=0 of this tile.
            if (nt * NGRP >= u0) {
                const float b00 = bias[n0c + rr];
                const float b01 = bias[n0c + rr + 8];
                const float b10 = bias[n0c + rr + 16];
                const float b11 = bias[n0c + rr + 24];
                #pragma unroll
                for (int ntl = 0; ntl < 4; ntl++) {
                    acc[0][ntl][0] += b00; acc[0][ntl][1] += b00;
                    acc[0][ntl][2] += b01; acc[0][ntl][3] += b01;
                    acc[1][ntl][0] += b10; acc[1][ntl][1] += b10;
                    acc[1][ntl][2] += b11; acc[1][ntl][3] += b11;
                }
            }
            #pragma unroll
            for (int mt = 0; mt < 2; mt++) {
                #pragma unroll
                for (int ntl = 0; ntl < 4; ntl++) {
                    #pragma unroll
                    for (int i = 0; i < 4; i++) {
                        const int row_out = n0c + wm * 32 + mt * 16 + (lane >> 2) + ((i >= 2) ? 8 : 0);
                        const int tok     = wn * 32 + ntl * 8 + (lane & 3) * 2 + (i & 1);
                        atomicAdd(&out[(size_t)tok * N_DIM + row_out], acc[mt][ntl][i]);
                        acc[mt][ntl][i] = 0.0f;
                    }
                }
            }
        }
    }
}

// ---------------- host launch ----------------
typedef CUresult (*tmap_encode_fn)(
    CUtensorMap*, CUtensorMapDataType, cuuint32_t, void*,
    const cuuint64_t*, const cuuint64_t*, const cuuint32_t*, const cuuint32_t*,
    CUtensorMapInterleave, CUtensorMapSwizzle, CUtensorMapL2promotion, CUtensorMapFloatOOBfill);

extern "C" void kernel_launch(void* const* d_in, const int* in_sizes, int n_in,
                              void* d_out, int out_size)
{
    const float* x  = (const float*)d_in[0];
    void*        w  = (void*)d_in[1];
    const float* ws = (const float*)d_in[2];
    const float* bs = (const float*)d_in[3];
    float* out = (float*)d_out;

    void* fp = nullptr;
    cudaDriverEntryPointQueryResult qres;
    cudaGetDriverEntryPointByVersion("cuTensorMapEncodeTiled", &fp, 12000,
                                     cudaEnableDefault, &qres);
    if (!fp || qres != cudaDriverEntryPointSuccess) return;
    tmap_encode_fn enc = (tmap_encode_fn)fp;

    void* xr_ptr = nullptr;
    cudaGetSymbolAddress(&xr_ptr, g_x_r);

    CUtensorMap w_map, x_map;
    {
        cuuint64_t dims[2]  = {K_DIM, N_DIM};
        cuuint64_t strd[1]  = {K_DIM * 4};
        cuuint32_t box[2]   = {32, 128};
        cuuint32_t estr[2]  = {1, 1};
        enc(&w_map, CU_TENSOR_MAP_DATA_TYPE_FLOAT32, 2, w, dims, strd, box, estr,
            CU_TENSOR_MAP_INTERLEAVE_NONE, CU_TENSOR_MAP_SWIZZLE_128B,
            CU_TENSOR_MAP_L2_PROMOTION_L2_128B, CU_TENSOR_MAP_FLOAT_OOB_FILL_NONE);
    }
    {
        cuuint64_t dims[2]  = {K_DIM, M_TOK};
        cuuint64_t strd[1]  = {K_DIM * 4};
        cuuint32_t box[2]   = {32, 64};
        cuuint32_t estr[2]  = {1, 1};
        enc(&x_map, CU_TENSOR_MAP_DATA_TYPE_FLOAT32, 2, xr_ptr, dims, strd, box, estr,
            CU_TENSOR_MAP_INTERLEAVE_NONE, CU_TENSOR_MAP_SWIZZLE_128B,
            CU_TENSOR_MAP_L2_PROMOTION_L2_128B, CU_TENSOR_MAP_FLOAT_OOB_FILL_NONE);
    }

    cudaFuncSetAttribute(qlin_kernel, cudaFuncAttributeMaxDynamicSharedMemorySize, SM_TOTAL);

    cudaMemsetAsync(out, 0, (size_t)M_TOK * N_DIM * sizeof(float));
    prep_kernel<<<(X4_CNT + 255) / 256, 256>>>((const float4*)x);
    qlin_kernel<<<NUM_CTAS, THREADS, SM_TOTAL>>>(ws, bs, out, w_map, x_map);
}